// round 4
// baseline (speedup 1.0000x reference)
#include <cuda_runtime.h>
#include <math.h>

#define NFFT  4096
#define LOGN  12
#define LSEQ  2048
#define BB    32
#define DD    32
#define KK    32
#define OO    32
#define JH    28      // truncated impulse-response length of y-recurrence
#define FH    2064    // padded half-spectrum bin count (>= 2049, 128B-aligned rows)
#define TFIX  32      // first TFIX timesteps recomputed exactly (alias reaches t<=26)

// ---------------- scratch (device globals; no allocation allowed) ------------
__device__ float2 g_U[BB][DD][FH];     // FFT of inputs      (b, d, f<=half)
__device__ float2 g_G[BB][OO][FH];     // output spectra     (b, o, f<=half)
__device__ float2 g_W[FH][DD][OO];     // combined filter    (f<=half, d, o)
__device__ float2 g_V[KK][FH];         // FFT of eig_vecs    (k, f<=half)
__device__ float  g_h[JH][OO][OO];     // impulse response of recurrence
__device__ float  g_Fs[TFIX][DD][OO];  // time-domain F for the fixup region
__device__ float2 g_tw[NFFT];          // twiddles, per-stage layout [half + p]

// ---------------- helpers ----------------------------------------------------
__device__ __forceinline__ float2 cmulf(float2 a, float2 b) {
    return make_float2(a.x*b.x - a.y*b.y, a.x*b.y + a.y*b.x);
}

// In-place radix-4 DIT FFT over 4096 complex values in shared memory.
// inverse=0 forward (numpy convention), inverse=1 conjugated (scale by caller).
// blockDim.x must be 1024. x must be 16-byte aligned.
__device__ void fft_shared(float2* x, int inverse) {
    int tid = threadIdx.x;
    __syncthreads();
    // base-4 digit-reversal permutation
    for (int i = tid; i < NFFT; i += 1024) {
        unsigned r = __brev((unsigned)i) >> 20;
        r = ((r & 0x555u) << 1) | ((r >> 1) & 0x555u);
        if ((unsigned)i < r) { float2 t = x[i]; x[i] = x[r]; x[r] = t; }
    }
    __syncthreads();
    // stage 0: q=1, twiddles are 1; vectorized float4
    {
        float4* x4 = reinterpret_cast<float4*>(x);
        float4 lo = x4[2 * tid];
        float4 hi = x4[2 * tid + 1];
        float2 A = make_float2(lo.x, lo.y), B = make_float2(lo.z, lo.w);
        float2 C = make_float2(hi.x, hi.y), D = make_float2(hi.z, hi.w);
        float2 t0 = make_float2(A.x + C.x, A.y + C.y);
        float2 t1 = make_float2(A.x - C.x, A.y - C.y);
        float2 t2 = make_float2(B.x + D.x, B.y + D.y);
        float2 t3 = make_float2(B.x - D.x, B.y - D.y);
        float2 y0 = make_float2(t0.x + t2.x, t0.y + t2.y);
        float2 y2 = make_float2(t0.x - t2.x, t0.y - t2.y);
        float2 y1, y3;
        if (!inverse) {
            y1 = make_float2(t1.x + t3.y, t1.y - t3.x);
            y3 = make_float2(t1.x - t3.y, t1.y + t3.x);
        } else {
            y1 = make_float2(t1.x - t3.y, t1.y + t3.x);
            y3 = make_float2(t1.x + t3.y, t1.y - t3.x);
        }
        x4[2 * tid]     = make_float4(y0.x, y0.y, y1.x, y1.y);
        x4[2 * tid + 1] = make_float4(y2.x, y2.y, y3.x, y3.y);
    }
    __syncthreads();
    // stage 1 (q=4): j-slot rotated by g&3 to cut 8-way bank conflicts to 2-way
    {
        const int q = 4;
        int p = tid & 3;
        int g = tid >> 2;
        int base = (g << 4) + p;
        int rot = g & 3;
        float2 w1 = __ldg(&g_tw[8 + p]);
        float2 w2 = __ldg(&g_tw[4 + p]);
        if (inverse) { w1.y = -w1.y; w2.y = -w2.y; }
        float2 w3 = cmulf(w1, w2);
        // rotated loads: instruction c accesses slot (c+rot)&3
        float2 L0 = x[base + rot * q];
        float2 L1 = x[base + (((rot + 1) & 3)) * q];
        float2 L2 = x[base + (((rot + 2) & 3)) * q];
        float2 L3 = x[base + (((rot + 3) & 3)) * q];
        // unrotate: slot j lives in L_{(j-rot)&3}
        float2 A = (rot == 0) ? L0 : (rot == 1) ? L3 : (rot == 2) ? L2 : L1;
        float2 Bv= (rot == 0) ? L1 : (rot == 1) ? L0 : (rot == 2) ? L3 : L2;
        float2 Cv= (rot == 0) ? L2 : (rot == 1) ? L1 : (rot == 2) ? L0 : L3;
        float2 Dv= (rot == 0) ? L3 : (rot == 1) ? L2 : (rot == 2) ? L1 : L0;
        float2 B = cmulf(Bv, w1);
        float2 C = cmulf(Cv, w2);
        float2 D = cmulf(Dv, w3);
        float2 t0 = make_float2(A.x + C.x, A.y + C.y);
        float2 t1 = make_float2(A.x - C.x, A.y - C.y);
        float2 t2 = make_float2(B.x + D.x, B.y + D.y);
        float2 t3 = make_float2(B.x - D.x, B.y - D.y);
        float2 y0 = make_float2(t0.x + t2.x, t0.y + t2.y);
        float2 y2 = make_float2(t0.x - t2.x, t0.y - t2.y);
        float2 y1, y3;
        if (!inverse) {
            y1 = make_float2(t1.x + t3.y, t1.y - t3.x);
            y3 = make_float2(t1.x - t3.y, t1.y + t3.x);
        } else {
            y1 = make_float2(t1.x - t3.y, t1.y + t3.x);
            y3 = make_float2(t1.x + t3.y, t1.y - t3.x);
        }
        // rotated stores: instruction c writes slot (c+rot)&3
        float2 S0 = (rot == 0) ? y0 : (rot == 1) ? y1 : (rot == 2) ? y2 : y3;
        float2 S1 = (rot == 0) ? y1 : (rot == 1) ? y2 : (rot == 2) ? y3 : y0;
        float2 S2 = (rot == 0) ? y2 : (rot == 1) ? y3 : (rot == 2) ? y0 : y1;
        float2 S3 = (rot == 0) ? y3 : (rot == 1) ? y0 : (rot == 2) ? y1 : y2;
        x[base + rot * q]               = S0;
        x[base + ((rot + 1) & 3) * q]   = S1;
        x[base + ((rot + 2) & 3) * q]   = S2;
        x[base + ((rot + 3) & 3) * q]   = S3;
    }
    __syncthreads();
    // stages 2..5
    for (int s = 2; s < 6; s++) {
        int q = 1 << (2 * s);
        int p = tid & (q - 1);
        int g = tid >> (2 * s);
        int base = (g << (2 * s + 2)) + p;
        float2 w1 = __ldg(&g_tw[2 * q + p]);
        float2 w2 = __ldg(&g_tw[q + p]);
        if (inverse) { w1.y = -w1.y; w2.y = -w2.y; }
        float2 w3 = cmulf(w1, w2);
        float2 A = x[base];
        float2 B = cmulf(x[base + q], w1);
        float2 C = cmulf(x[base + 2 * q], w2);
        float2 D = cmulf(x[base + 3 * q], w3);
        float2 t0 = make_float2(A.x + C.x, A.y + C.y);
        float2 t1 = make_float2(A.x - C.x, A.y - C.y);
        float2 t2 = make_float2(B.x + D.x, B.y + D.y);
        float2 t3 = make_float2(B.x - D.x, B.y - D.y);
        x[base]         = make_float2(t0.x + t2.x, t0.y + t2.y);
        x[base + 2 * q] = make_float2(t0.x - t2.x, t0.y - t2.y);
        if (!inverse) {
            x[base + q]     = make_float2(t1.x + t3.y, t1.y - t3.x);
            x[base + 3 * q] = make_float2(t1.x - t3.y, t1.y + t3.x);
        } else {
            x[base + q]     = make_float2(t1.x - t3.y, t1.y + t3.x);
            x[base + 3 * q] = make_float2(t1.x + t3.y, t1.y - t3.x);
        }
        __syncthreads();
    }
}

// ---------------- kernel: fused preamble (twiddles + h-recurrence + Fs) ------
// blocks 0..TFIX-1: g_Fs;  blocks TFIX..TFIX+3: g_tw;  block TFIX+4: g_h
__global__ void k_pre(const float* __restrict__ m_y,
                      const float* __restrict__ eig_vals,
                      const float* __restrict__ ev,
                      const float* __restrict__ m_phi) {
    int blk = blockIdx.x;
    int tid = threadIdx.x;                  // 1024
    if (blk < TFIX) {
        __shared__ float sc[KK];
        __shared__ float vv[KK];
        int s = blk;
        if (tid < KK) {
            sc[tid] = sqrtf(sqrtf(eig_vals[tid]));
            vv[tid] = ev[(size_t)s * KK + tid];
        }
        __syncthreads();
        int d = tid >> 5, o = tid & 31;
        float acc = 0.f;
        #pragma unroll
        for (int k = 0; k < KK; k++)
            acc += sc[k] * vv[k] * m_phi[(k * DD + d) * OO + o];
        g_Fs[s][d][o] = acc;
    } else if (blk < TFIX + 4) {
        int i = (blk - TFIX) * 1024 + tid;
        if (i == 0) { g_tw[0] = make_float2(1.f, 0.f); return; }
        int s = 31 - __clz(i);
        int half = 1 << s;
        int p = i - half;
        float ang = -3.14159265358979323846f * (float)p / (float)half;
        float sn, cs; sincosf(ang, &sn, &cs);
        g_tw[i] = make_float2(cs, sn);
    } else {
        __shared__ float M1[OO * OO], M2[OO * OO], hp[OO * OO], hp2[OO * OO];
        int o = tid >> 5, i = tid & 31;
        M1[o * 32 + i] = m_y[o * 64 + i];
        M2[o * 32 + i] = m_y[o * 64 + 32 + i];
        float h0 = (o == i) ? 1.f : 0.f;
        hp2[o * 32 + i] = h0;
        g_h[0][o][i] = h0;
        hp[o * 32 + i] = m_y[o * 64 + i];
        g_h[1][o][i] = m_y[o * 64 + i];
        __syncthreads();
        for (int j = 2; j < JH; j++) {
            float acc = 0.f;
            #pragma unroll
            for (int t = 0; t < 32; t++)
                acc += M1[o * 32 + t] * hp[t * 32 + i] + M2[o * 32 + t] * hp2[t * 32 + i];
            __syncthreads();
            hp2[o * 32 + i] = hp[o * 32 + i];
            __syncthreads();
            hp[o * 32 + i] = acc;
            g_h[j][o][i] = acc;
            __syncthreads();
        }
    }
}

// ---------------- kernel: FFT of eig_vecs (pack column pairs) ----------------
__global__ void k_fft_v(const float* __restrict__ ev) {
    __shared__ __align__(16) float2 sh[NFFT];
    int kp = blockIdx.x;                    // 0..15 -> filters 2kp, 2kp+1
    int tid = threadIdx.x;                  // 1024
    for (int t = tid; t < LSEQ; t += 1024) {
        const float2 v = *reinterpret_cast<const float2*>(ev + (size_t)t * KK + 2 * kp);
        sh[t] = v;
    }
    for (int t = LSEQ + tid; t < NFFT; t += 1024) sh[t] = make_float2(0.f, 0.f);
    fft_shared(sh, 0);
    for (int f = tid; f < FH; f += 1024) {
        float2 zf = sh[f];
        float2 zm = sh[(NFFT - f) & (NFFT - 1)];
        g_V[2 * kp][f]     = make_float2(0.5f * (zf.x + zm.x), 0.5f * (zf.y - zm.y));
        g_V[2 * kp + 1][f] = make_float2(0.5f * (zf.y + zm.y), 0.5f * (zm.x - zf.x));
    }
}

// ---------------- kernel: fused combined filter W (4 bins / block) -----------
// Hhat[f,o,o'] = sum_j h_j[o,o'] e^{-i 2pi f j / N}
// FA[f,d,q]    = sum_k (lam_k^.25 V[f,k]) m_phi[k*D+d,q] + sum_j m_u[q,d,j] e^{-i 2pi f j/N}
// W[f,d,o]     = sum_q FA[f,d,q] * Hhat[f,o,q]
__global__ void __launch_bounds__(1024, 1)
k_W(const float* __restrict__ eig_vals,
    const float* __restrict__ m_phi,
    const float* __restrict__ m_u) {
    extern __shared__ __align__(16) char sm_raw[];
    float2 (*Hs)[OO][OO + 1] = reinterpret_cast<float2(*)[OO][OO + 1]>(sm_raw);            // 33792 B
    float2 (*FAs)[DD][OO]    = reinterpret_cast<float2(*)[DD][OO]>(sm_raw + 33792);        // 32768 B
    float2 (*sv)[KK]         = reinterpret_cast<float2(*)[KK]>(sm_raw + 33792 + 32768);    // 1024 B
    int f0 = blockIdx.x * 4;
    int tid = threadIdx.x;                  // 1024
    int o = tid >> 5, i = tid & 31;

    float2 w[4];
    #pragma unroll
    for (int b = 0; b < 4; b++) {
        float s, c;
        sincosf(-6.283185307179586f * (float)(f0 + b) / (float)NFFT, &s, &c);
        w[b] = make_float2(c, s);
    }

    // Hhat for 4 bins (thread owns element (o, i))
    float2 acc[4], cur[4];
    #pragma unroll
    for (int b = 0; b < 4; b++) { acc[b] = make_float2(0.f, 0.f); cur[b] = make_float2(1.f, 0.f); }
    #pragma unroll 4
    for (int j = 0; j < JH; j++) {
        float hv = g_h[j][o][i];
        #pragma unroll
        for (int b = 0; b < 4; b++) {
            acc[b].x += hv * cur[b].x; acc[b].y += hv * cur[b].y;
            cur[b] = cmulf(cur[b], w[b]);
        }
    }
    #pragma unroll
    for (int b = 0; b < 4; b++) Hs[b][i][o] = acc[b];   // transposed store

    if (tid < 128) {
        int bin = tid >> 5, k = tid & 31;
        float sc = sqrtf(sqrtf(eig_vals[k]));
        float2 v = g_V[k][f0 + bin];
        sv[bin][k] = make_float2(v.x * sc, v.y * sc);
    }
    __syncthreads();

    // FA for 4 bins (thread owns (d=o, q=i))
    int d = o, q = i;
    float2 fa[4];
    #pragma unroll
    for (int b = 0; b < 4; b++) fa[b] = make_float2(0.f, 0.f);
    #pragma unroll 4
    for (int k = 0; k < KK; k++) {
        float m = m_phi[(k * DD + d) * OO + q];
        #pragma unroll
        for (int b = 0; b < 4; b++) {
            fa[b].x += sv[b][k].x * m;
            fa[b].y += sv[b][k].y * m;
        }
    }
    float a0 = m_u[(q * DD + d) * 3 + 0];
    float a1 = m_u[(q * DD + d) * 3 + 1];
    float a2 = m_u[(q * DD + d) * 3 + 2];
    #pragma unroll
    for (int b = 0; b < 4; b++) {
        float c2 = w[b].x * w[b].x - w[b].y * w[b].y;
        float s2 = 2.f * w[b].x * w[b].y;
        fa[b].x += a0 + a1 * w[b].x + a2 * c2;
        fa[b].y += a1 * w[b].y + a2 * s2;
        FAs[b][d][q] = fa[b];
    }
    __syncthreads();

    // W[d, o] = sum_t FA[d, t] * Hhat[o, t]   (Hs holds Hhat^T: Hs[t][o])
    float2 r[4];
    #pragma unroll
    for (int b = 0; b < 4; b++) r[b] = make_float2(0.f, 0.f);
    #pragma unroll 4
    for (int t = 0; t < OO; t++) {
        #pragma unroll
        for (int b = 0; b < 4; b++) {
            float2 A = FAs[b][d][t];
            float2 h = Hs[b][t][i];
            r[b].x += A.x * h.x - A.y * h.y;
            r[b].y += A.x * h.y + A.y * h.x;
        }
    }
    #pragma unroll
    for (int b = 0; b < 4; b++) g_W[f0 + b][d][i] = r[b];
}

// ---------------- kernel: FFT of inputs (pack channel pairs) -----------------
__global__ void k_fft_fwd(const float* __restrict__ inp) {
    __shared__ __align__(16) float2 sh[NFFT];
    int blk = blockIdx.x;                   // 512: (b, dpair)
    int b = blk >> 4, dp = blk & 15;
    int tid = threadIdx.x;                  // 1024
    for (int t = tid; t < LSEQ; t += 1024) {
        const float2 v = *reinterpret_cast<const float2*>(
            inp + ((size_t)(b * LSEQ + t)) * DD + 2 * dp);
        sh[t] = v;
    }
    for (int t = LSEQ + tid; t < NFFT; t += 1024) sh[t] = make_float2(0.f, 0.f);
    fft_shared(sh, 0);
    for (int f = tid; f < FH; f += 1024) {
        float2 zf = sh[f];
        float2 zm = sh[(NFFT - f) & (NFFT - 1)];
        g_U[b][2 * dp][f]     = make_float2(0.5f * (zf.x + zm.x), 0.5f * (zf.y - zm.y));
        g_U[b][2 * dp + 1][f] = make_float2(0.5f * (zf.y + zm.y), 0.5f * (zm.x - zf.x));
    }
}

// ---------------- kernel: per-bin complex matvec G = U * W -------------------
__global__ void k_mul() {
    __shared__ __align__(16) float2 Us[BB][4][DD + 2];   // ~34.8 KB
    int tid = threadIdx.x;            // 256
    int f0 = blockIdx.x * 4;
    #pragma unroll
    for (int k = 0; k < 4; k++) {
        int pair = tid + k * 256;     // pair = b*32 + d
        int b = pair >> 5, d = pair & 31;
        const float4* src = reinterpret_cast<const float4*>(&g_U[b][d][f0]);
        float4 v0 = src[0], v1 = src[1];
        Us[b][0][d] = make_float2(v0.x, v0.y);
        Us[b][1][d] = make_float2(v0.z, v0.w);
        Us[b][2][d] = make_float2(v1.x, v1.y);
        Us[b][3][d] = make_float2(v1.z, v1.w);
    }
    int bh = tid >> 7;
    int o  = (tid >> 2) & 31;
    int fi = tid & 3;
    int f  = f0 + fi;
    float2 Wreg[DD];
    #pragma unroll
    for (int d = 0; d < DD; d++) Wreg[d] = g_W[f][d][o];
    __syncthreads();
    for (int bi = 0; bi < 16; bi++) {
        int b = bh * 16 + bi;
        float2 a0 = make_float2(0.f, 0.f), a1 = a0;
        const float4* up = reinterpret_cast<const float4*>(&Us[b][fi][0]);
        #pragma unroll
        for (int d2 = 0; d2 < DD / 2; d2++) {
            float4 uv = up[d2];
            float2 w0 = Wreg[2 * d2], w1 = Wreg[2 * d2 + 1];
            a0.x += uv.x * w0.x - uv.y * w0.y;
            a0.y += uv.x * w0.y + uv.y * w0.x;
            a1.x += uv.z * w1.x - uv.w * w1.y;
            a1.y += uv.z * w1.y + uv.w * w1.x;
        }
        g_G[b][o][f] = make_float2(a0.x + a1.x, a0.y + a1.y);
    }
}

// ---------------- kernel: inverse FFT (Hermitian reconstruct + pack) ---------
__global__ void k_ifft(float* __restrict__ out) {
    __shared__ __align__(16) float2 sh[NFFT];
    int blk = blockIdx.x;                   // 512: (b, opair)
    int b = blk >> 4, op = blk & 15;
    int tid = threadIdx.x;                  // 1024
    for (int f = tid; f < NFFT; f += 1024) {
        int mir = f > NFFT / 2;
        int fm = mir ? NFFT - f : f;
        float sgn = mir ? -1.f : 1.f;
        float2 a = g_G[b][2 * op][fm];
        float2 c = g_G[b][2 * op + 1][fm];
        a.y *= sgn; c.y *= sgn;
        sh[f] = make_float2(a.x - c.y, a.y + c.x);
    }
    fft_shared(sh, 1);
    const float inv = 1.f / (float)NFFT;
    for (int t = tid; t < LSEQ; t += 1024) {
        float2 z = sh[t];
        float2* p = reinterpret_cast<float2*>(out + ((size_t)(b * LSEQ + t)) * OO + 2 * op);
        *p = make_float2(z.x * inv, z.y * inv);
    }
}

// ---------------- kernel: exact recompute of y for t < TFIX ------------------
__global__ void k_fix(const float* __restrict__ inp,
                      const float* __restrict__ m_u,
                      const float* __restrict__ m_y,
                      float* __restrict__ out) {
    __shared__ float u[TFIX * DD];
    __shared__ float Fsh[DD * OO];
    __shared__ float delta[TFIX * OO];
    __shared__ float y1[OO], y2[OO];
    int b = blockIdx.x, tid = threadIdx.x;  // 256
    for (int idx = tid; idx < TFIX * DD; idx += 256)
        u[idx] = inp[(size_t)b * LSEQ * DD + idx];
    __syncthreads();
    float acc[4];
    #pragma unroll
    for (int r = 0; r < 4; r++) {
        int idx = tid + r * 256;
        int t = idx >> 5, o = idx & 31;
        float a = 0.f;
        for (int j = 0; j < 3; j++) {
            if (t >= j) {
                #pragma unroll
                for (int i = 0; i < DD; i++)
                    a += m_u[(o * DD + i) * 3 + j] * u[(t - j) * DD + i];
            }
        }
        acc[r] = a;
    }
    for (int s = 0; s < TFIX; s++) {
        const float* fp = &g_Fs[s][0][0];
        for (int idx = tid; idx < DD * OO; idx += 256) Fsh[idx] = fp[idx];
        __syncthreads();
        #pragma unroll
        for (int r = 0; r < 4; r++) {
            int idx = tid + r * 256;
            int t = idx >> 5, o = idx & 31;
            if (t >= s) {
                float a = acc[r];
                const float* ur = &u[(t - s) * DD];
                #pragma unroll
                for (int d = 0; d < DD; d++)
                    a += ur[d] * Fsh[d * OO + o];
                acc[r] = a;
            }
        }
        __syncthreads();
    }
    #pragma unroll
    for (int r = 0; r < 4; r++) { int idx = tid + r * 256; delta[idx] = acc[r]; }
    __syncthreads();
    if (tid < OO) {
        int o = tid;
        y1[o] = 0.f; y2[o] = 0.f;
        __syncwarp();
        for (int t = 0; t < TFIX; t++) {
            float a = delta[t * OO + o];
            #pragma unroll
            for (int i = 0; i < OO; i++)
                a += m_y[o * 64 + i] * y1[i] + m_y[o * 64 + 32 + i] * y2[i];
            __syncwarp();
            y2[o] = y1[o];
            __syncwarp();
            y1[o] = a;
            __syncwarp();
            out[((size_t)(b * LSEQ + t)) * OO + o] = a;
        }
    }
}

// ---------------- launch ------------------------------------------------------
extern "C" void kernel_launch(void* const* d_in, const int* in_sizes, int n_in,
                              void* d_out, int out_size) {
    const float* inputs  = (const float*)d_in[0];
    const float* eigvals = (const float*)d_in[1];
    const float* eigvecs = (const float*)d_in[2];
    const float* m_u     = (const float*)d_in[3];
    const float* m_phi   = (const float*)d_in[4];
    const float* m_y     = (const float*)d_in[5];
    float* out = (float*)d_out;

    const int KW_SMEM = 33792 + 32768 + 1024;   // 67584 B
    cudaFuncSetAttribute(k_W, cudaFuncAttributeMaxDynamicSharedMemorySize, KW_SMEM);

    k_pre    <<<TFIX + 5, 1024>>>(m_y, eigvals, eigvecs, m_phi);
    k_fft_v  <<<KK / 2, 1024>>>(eigvecs);
    k_fft_fwd<<<BB * DD / 2, 1024>>>(inputs);
    k_W      <<<FH / 4, 1024, KW_SMEM>>>(eigvals, m_phi, m_u);
    k_mul    <<<FH / 4, 256>>>();
    k_ifft   <<<BB * OO / 2, 1024>>>(out);
    k_fix    <<<BB, 256>>>(inputs, m_u, m_y, out);
}

// round 5
// speedup vs baseline: 1.0814x; 1.0814x over previous
#include <cuda_runtime.h>
#include <math.h>

#define NFFT  4096
#define LOGN  12
#define LSEQ  2048
#define BB    32
#define DD    32
#define KK    32
#define OO    32
#define JH    28      // truncated impulse-response length of y-recurrence
#define FH    2064    // padded half-spectrum bin count (>= 2049, 128B-aligned rows)
#define TFIX  32      // first TFIX timesteps recomputed exactly (alias reaches t<=26)

// ---------------- scratch (device globals; no allocation allowed) ------------
__device__ float2 g_U[BB][DD][FH];     // FFT of inputs      (b, d, f<=half)
__device__ float2 g_G[BB][OO][FH];     // output spectra     (b, o, f<=half)
__device__ float2 g_W[FH][DD][OO];     // combined filter    (f<=half, d, o)
__device__ float2 g_V[KK][FH];         // FFT of eig_vecs    (k, f<=half)
__device__ float  g_h[JH][OO][OO];     // impulse response of recurrence
__device__ float  g_Fs[TFIX][DD][OO];  // time-domain F for the fixup region
__device__ float2 g_tw[NFFT];          // twiddles, per-stage layout [half + p]

// ---------------- helpers ----------------------------------------------------
__device__ __forceinline__ float2 cmulf(float2 a, float2 b) {
    return make_float2(a.x*b.x - a.y*b.y, a.x*b.y + a.y*b.x);
}

// In-place radix-4 DIT FFT over 4096 complex values in shared memory.
// inverse=0 forward (numpy convention), inverse=1 conjugated (scale by caller).
// blockDim.x must be 1024. x must be 16-byte aligned.
__device__ void fft_shared(float2* x, int inverse) {
    int tid = threadIdx.x;
    __syncthreads();
    // base-4 digit-reversal permutation.
    // Lane remap: index bits {0,1} <- tid bits {0,1}, bits {8,9} <- tid bits {2,3},
    // bits {2..7} <- tid bits {4..9}, bits {10,11} <- iteration. This makes both
    // i and rev4(i) spread over 4 banks per 16-lane phase ((4,4) instead of (1,16)).
    #pragma unroll
    for (int k = 0; k < 4; k++) {
        int i = (tid & 3) | (((tid >> 2) & 3) << 8) | (((tid >> 4) & 63) << 2) | (k << 10);
        unsigned r = __brev((unsigned)i) >> 20;
        r = ((r & 0x555u) << 1) | ((r >> 1) & 0x555u);
        if ((unsigned)i < r) { float2 t = x[i]; x[i] = x[r]; x[r] = t; }
    }
    __syncthreads();
    // stage 0: q=1, twiddles are 1; vectorized float4
    {
        float4* x4 = reinterpret_cast<float4*>(x);
        float4 lo = x4[2 * tid];
        float4 hi = x4[2 * tid + 1];
        float2 A = make_float2(lo.x, lo.y), B = make_float2(lo.z, lo.w);
        float2 C = make_float2(hi.x, hi.y), D = make_float2(hi.z, hi.w);
        float2 t0 = make_float2(A.x + C.x, A.y + C.y);
        float2 t1 = make_float2(A.x - C.x, A.y - C.y);
        float2 t2 = make_float2(B.x + D.x, B.y + D.y);
        float2 t3 = make_float2(B.x - D.x, B.y - D.y);
        float2 y0 = make_float2(t0.x + t2.x, t0.y + t2.y);
        float2 y2 = make_float2(t0.x - t2.x, t0.y - t2.y);
        float2 y1, y3;
        if (!inverse) {
            y1 = make_float2(t1.x + t3.y, t1.y - t3.x);
            y3 = make_float2(t1.x - t3.y, t1.y + t3.x);
        } else {
            y1 = make_float2(t1.x - t3.y, t1.y + t3.x);
            y3 = make_float2(t1.x + t3.y, t1.y - t3.x);
        }
        x4[2 * tid]     = make_float4(y0.x, y0.y, y1.x, y1.y);
        x4[2 * tid + 1] = make_float4(y2.x, y2.y, y3.x, y3.y);
    }
    __syncthreads();
    // stages 1..5
    for (int s = 1; s < 6; s++) {
        int q = 1 << (2 * s);
        int p = tid & (q - 1);
        int g = tid >> (2 * s);
        int base = (g << (2 * s + 2)) + p;
        float2 w1 = __ldg(&g_tw[2 * q + p]);
        float2 w2 = __ldg(&g_tw[q + p]);
        if (inverse) { w1.y = -w1.y; w2.y = -w2.y; }
        float2 w3 = cmulf(w1, w2);
        float2 A = x[base];
        float2 B = cmulf(x[base + q], w1);
        float2 C = cmulf(x[base + 2 * q], w2);
        float2 D = cmulf(x[base + 3 * q], w3);
        float2 t0 = make_float2(A.x + C.x, A.y + C.y);
        float2 t1 = make_float2(A.x - C.x, A.y - C.y);
        float2 t2 = make_float2(B.x + D.x, B.y + D.y);
        float2 t3 = make_float2(B.x - D.x, B.y - D.y);
        x[base]         = make_float2(t0.x + t2.x, t0.y + t2.y);
        x[base + 2 * q] = make_float2(t0.x - t2.x, t0.y - t2.y);
        if (!inverse) {
            x[base + q]     = make_float2(t1.x + t3.y, t1.y - t3.x);
            x[base + 3 * q] = make_float2(t1.x - t3.y, t1.y + t3.x);
        } else {
            x[base + q]     = make_float2(t1.x - t3.y, t1.y + t3.x);
            x[base + 3 * q] = make_float2(t1.x + t3.y, t1.y - t3.x);
        }
        __syncthreads();
    }
}

// ---------------- kernel: fused preamble (twiddles + h-recurrence + Fs) ------
// blocks 0..TFIX-1: g_Fs;  blocks TFIX..TFIX+3: g_tw;  block TFIX+4: g_h
__global__ void k_pre(const float* __restrict__ m_y,
                      const float* __restrict__ eig_vals,
                      const float* __restrict__ ev,
                      const float* __restrict__ m_phi) {
    int blk = blockIdx.x;
    int tid = threadIdx.x;                  // 1024
    if (blk < TFIX) {
        __shared__ float sc[KK];
        __shared__ float vv[KK];
        int s = blk;
        if (tid < KK) {
            sc[tid] = sqrtf(sqrtf(eig_vals[tid]));
            vv[tid] = ev[(size_t)s * KK + tid];
        }
        __syncthreads();
        int d = tid >> 5, o = tid & 31;
        float acc = 0.f;
        #pragma unroll
        for (int k = 0; k < KK; k++)
            acc += sc[k] * vv[k] * m_phi[(k * DD + d) * OO + o];
        g_Fs[s][d][o] = acc;
    } else if (blk < TFIX + 4) {
        int i = (blk - TFIX) * 1024 + tid;
        if (i == 0) { g_tw[0] = make_float2(1.f, 0.f); return; }
        int s = 31 - __clz(i);
        int half = 1 << s;
        int p = i - half;
        float ang = -3.14159265358979323846f * (float)p / (float)half;
        float sn, cs; sincosf(ang, &sn, &cs);
        g_tw[i] = make_float2(cs, sn);
    } else {
        __shared__ float M1[OO * OO], M2[OO * OO], hp[OO * OO], hp2[OO * OO];
        int o = tid >> 5, i = tid & 31;
        M1[o * 32 + i] = m_y[o * 64 + i];
        M2[o * 32 + i] = m_y[o * 64 + 32 + i];
        float h0 = (o == i) ? 1.f : 0.f;
        hp2[o * 32 + i] = h0;
        g_h[0][o][i] = h0;
        hp[o * 32 + i] = m_y[o * 64 + i];
        g_h[1][o][i] = m_y[o * 64 + i];
        __syncthreads();
        for (int j = 2; j < JH; j++) {
            float acc = 0.f;
            #pragma unroll
            for (int t = 0; t < 32; t++)
                acc += M1[o * 32 + t] * hp[t * 32 + i] + M2[o * 32 + t] * hp2[t * 32 + i];
            __syncthreads();
            hp2[o * 32 + i] = hp[o * 32 + i];
            __syncthreads();
            hp[o * 32 + i] = acc;
            g_h[j][o][i] = acc;
            __syncthreads();
        }
    }
}

// ---------------- kernel: forward FFTs (inputs + eig_vecs fused) -------------
// blocks 0..511: inputs (b = blk>>4, dpair = blk&15)
// blocks 512..527: eig_vecs column pairs (kp = blk-512)
__global__ void k_fft_fwd(const float* __restrict__ inp,
                          const float* __restrict__ ev) {
    __shared__ __align__(16) float2 sh[NFFT];
    int blk = blockIdx.x;
    int tid = threadIdx.x;                  // 1024
    if (blk < 512) {
        int b = blk >> 4, dp = blk & 15;
        for (int t = tid; t < LSEQ; t += 1024) {
            const float2 v = *reinterpret_cast<const float2*>(
                inp + ((size_t)(b * LSEQ + t)) * DD + 2 * dp);
            sh[t] = v;
        }
        for (int t = LSEQ + tid; t < NFFT; t += 1024) sh[t] = make_float2(0.f, 0.f);
        fft_shared(sh, 0);
        for (int f = tid; f < FH; f += 1024) {
            float2 zf = sh[f];
            float2 zm = sh[(NFFT - f) & (NFFT - 1)];
            g_U[b][2 * dp][f]     = make_float2(0.5f * (zf.x + zm.x), 0.5f * (zf.y - zm.y));
            g_U[b][2 * dp + 1][f] = make_float2(0.5f * (zf.y + zm.y), 0.5f * (zm.x - zf.x));
        }
    } else {
        int kp = blk - 512;                 // 0..15 -> filters 2kp, 2kp+1
        for (int t = tid; t < LSEQ; t += 1024) {
            const float2 v = *reinterpret_cast<const float2*>(ev + (size_t)t * KK + 2 * kp);
            sh[t] = v;
        }
        for (int t = LSEQ + tid; t < NFFT; t += 1024) sh[t] = make_float2(0.f, 0.f);
        fft_shared(sh, 0);
        for (int f = tid; f < FH; f += 1024) {
            float2 zf = sh[f];
            float2 zm = sh[(NFFT - f) & (NFFT - 1)];
            g_V[2 * kp][f]     = make_float2(0.5f * (zf.x + zm.x), 0.5f * (zf.y - zm.y));
            g_V[2 * kp + 1][f] = make_float2(0.5f * (zf.y + zm.y), 0.5f * (zm.x - zf.x));
        }
    }
}

// ---------------- kernel: fused combined filter W (2 bins / block) -----------
// Hhat[f,o,o'] = sum_j h_j[o,o'] e^{-i 2pi f j / N}
// FA[f,d,q]    = sum_k (lam_k^.25 V[f,k]) m_phi[k*D+d,q] + sum_j m_u[q,d,j] e^{-i 2pi f j/N}
// W[f,d,o]     = sum_q FA[f,d,q] * Hhat[f,o,q]
__global__ void k_W(const float* __restrict__ eig_vals,
                    const float* __restrict__ m_phi,
                    const float* __restrict__ m_u) {
    __shared__ float2 Hs[2][OO][OO + 1];    // transposed: Hs[bin][o'][o]
    __shared__ float2 FAs[2][DD][OO];
    __shared__ float2 sv[2][KK];
    int f0 = blockIdx.x * 2;
    int tid = threadIdx.x;                  // 1024
    int o = tid >> 5, i = tid & 31;

    float s0, c0, s1, c1;
    sincosf(-6.283185307179586f * (float)f0 / (float)NFFT, &s0, &c0);
    sincosf(-6.283185307179586f * (float)(f0 + 1) / (float)NFFT, &s1, &c1);
    float2 w0 = make_float2(c0, s0), w1 = make_float2(c1, s1);

    float2 acc0 = make_float2(0.f, 0.f), acc1 = acc0;
    float2 cur0 = make_float2(1.f, 0.f), cur1 = cur0;
    #pragma unroll 4
    for (int j = 0; j < JH; j++) {
        float hv = g_h[j][o][i];
        acc0.x += hv * cur0.x; acc0.y += hv * cur0.y;
        acc1.x += hv * cur1.x; acc1.y += hv * cur1.y;
        cur0 = cmulf(cur0, w0);
        cur1 = cmulf(cur1, w1);
    }
    Hs[0][i][o] = acc0;
    Hs[1][i][o] = acc1;

    if (tid < 64) {
        int bin = tid >> 5, k = tid & 31;
        float sc = sqrtf(sqrtf(eig_vals[k]));
        float2 v = g_V[k][f0 + bin];
        sv[bin][k] = make_float2(v.x * sc, v.y * sc);
    }
    __syncthreads();

    int d = o, q = i;
    float2 fa0 = make_float2(0.f, 0.f), fa1 = fa0;
    #pragma unroll 8
    for (int k = 0; k < KK; k++) {
        float m = m_phi[(k * DD + d) * OO + q];
        fa0.x += sv[0][k].x * m; fa0.y += sv[0][k].y * m;
        fa1.x += sv[1][k].x * m; fa1.y += sv[1][k].y * m;
    }
    float a0 = m_u[(q * DD + d) * 3 + 0];
    float a1 = m_u[(q * DD + d) * 3 + 1];
    float a2 = m_u[(q * DD + d) * 3 + 2];
    {
        float c2 = w0.x * w0.x - w0.y * w0.y, sn2 = 2.f * w0.x * w0.y;
        fa0.x += a0 + a1 * w0.x + a2 * c2;
        fa0.y += a1 * w0.y + a2 * sn2;
    }
    {
        float c2 = w1.x * w1.x - w1.y * w1.y, sn2 = 2.f * w1.x * w1.y;
        fa1.x += a0 + a1 * w1.x + a2 * c2;
        fa1.y += a1 * w1.y + a2 * sn2;
    }
    FAs[0][d][q] = fa0;
    FAs[1][d][q] = fa1;
    __syncthreads();

    float2 r0 = make_float2(0.f, 0.f), r1 = r0;
    #pragma unroll 8
    for (int t = 0; t < OO; t++) {
        float2 A = FAs[0][d][t];
        float2 h = Hs[0][t][i];
        r0.x += A.x * h.x - A.y * h.y;
        r0.y += A.x * h.y + A.y * h.x;
        float2 B = FAs[1][d][t];
        float2 g = Hs[1][t][i];
        r1.x += B.x * g.x - B.y * g.y;
        r1.y += B.x * g.y + B.y * g.x;
    }
    g_W[f0][d][i]     = r0;
    g_W[f0 + 1][d][i] = r1;
}

// ---------------- kernel: per-bin complex matvec G = U * W -------------------
__global__ void k_mul() {
    __shared__ __align__(16) float2 Us[BB][4][DD + 2];   // ~34.8 KB
    int tid = threadIdx.x;            // 256
    int f0 = blockIdx.x * 4;
    #pragma unroll
    for (int k = 0; k < 4; k++) {
        int pair = tid + k * 256;     // pair = b*32 + d
        int b = pair >> 5, d = pair & 31;
        const float4* src = reinterpret_cast<const float4*>(&g_U[b][d][f0]);
        float4 v0 = src[0], v1 = src[1];
        Us[b][0][d] = make_float2(v0.x, v0.y);
        Us[b][1][d] = make_float2(v0.z, v0.w);
        Us[b][2][d] = make_float2(v1.x, v1.y);
        Us[b][3][d] = make_float2(v1.z, v1.w);
    }
    int bh = tid >> 7;
    int o  = (tid >> 2) & 31;
    int fi = tid & 3;
    int f  = f0 + fi;
    float2 Wreg[DD];
    #pragma unroll
    for (int d = 0; d < DD; d++) Wreg[d] = g_W[f][d][o];
    __syncthreads();
    for (int bi = 0; bi < 16; bi++) {
        int b = bh * 16 + bi;
        float2 a0 = make_float2(0.f, 0.f), a1 = a0;
        const float4* up = reinterpret_cast<const float4*>(&Us[b][fi][0]);
        #pragma unroll
        for (int d2 = 0; d2 < DD / 2; d2++) {
            float4 uv = up[d2];
            float2 w0 = Wreg[2 * d2], w1 = Wreg[2 * d2 + 1];
            a0.x += uv.x * w0.x - uv.y * w0.y;
            a0.y += uv.x * w0.y + uv.y * w0.x;
            a1.x += uv.z * w1.x - uv.w * w1.y;
            a1.y += uv.z * w1.y + uv.w * w1.x;
        }
        g_G[b][o][f] = make_float2(a0.x + a1.x, a0.y + a1.y);
    }
}

// ---------------- kernel: inverse FFT (Hermitian reconstruct + pack) ---------
__global__ void k_ifft(float* __restrict__ out) {
    __shared__ __align__(16) float2 sh[NFFT];
    int blk = blockIdx.x;                   // 512: (b, opair)
    int b = blk >> 4, op = blk & 15;
    int tid = threadIdx.x;                  // 1024
    for (int f = tid; f < NFFT; f += 1024) {
        int mir = f > NFFT / 2;
        int fm = mir ? NFFT - f : f;
        float sgn = mir ? -1.f : 1.f;
        float2 a = g_G[b][2 * op][fm];
        float2 c = g_G[b][2 * op + 1][fm];
        a.y *= sgn; c.y *= sgn;
        sh[f] = make_float2(a.x - c.y, a.y + c.x);
    }
    fft_shared(sh, 1);
    const float inv = 1.f / (float)NFFT;
    for (int t = tid; t < LSEQ; t += 1024) {
        float2 z = sh[t];
        float2* p = reinterpret_cast<float2*>(out + ((size_t)(b * LSEQ + t)) * OO + 2 * op);
        *p = make_float2(z.x * inv, z.y * inv);
    }
}

// ---------------- kernel: exact recompute of y for t < TFIX ------------------
__global__ void k_fix(const float* __restrict__ inp,
                      const float* __restrict__ m_u,
                      const float* __restrict__ m_y,
                      float* __restrict__ out) {
    __shared__ float u[TFIX * DD];
    __shared__ float Fsh[DD * OO];
    __shared__ float delta[TFIX * OO];
    __shared__ float y1[OO], y2[OO];
    int b = blockIdx.x, tid = threadIdx.x;  // 256
    for (int idx = tid; idx < TFIX * DD; idx += 256)
        u[idx] = inp[(size_t)b * LSEQ * DD + idx];
    __syncthreads();
    float acc[4];
    #pragma unroll
    for (int r = 0; r < 4; r++) {
        int idx = tid + r * 256;
        int t = idx >> 5, o = idx & 31;
        float a = 0.f;
        for (int j = 0; j < 3; j++) {
            if (t >= j) {
                #pragma unroll
                for (int i = 0; i < DD; i++)
                    a += m_u[(o * DD + i) * 3 + j] * u[(t - j) * DD + i];
            }
        }
        acc[r] = a;
    }
    for (int s = 0; s < TFIX; s++) {
        const float* fp = &g_Fs[s][0][0];
        for (int idx = tid; idx < DD * OO; idx += 256) Fsh[idx] = fp[idx];
        __syncthreads();
        #pragma unroll
        for (int r = 0; r < 4; r++) {
            int idx = tid + r * 256;
            int t = idx >> 5, o = idx & 31;
            if (t >= s) {
                float a = acc[r];
                const float* ur = &u[(t - s) * DD];
                #pragma unroll
                for (int d = 0; d < DD; d++)
                    a += ur[d] * Fsh[d * OO + o];
                acc[r] = a;
            }
        }
        __syncthreads();
    }
    #pragma unroll
    for (int r = 0; r < 4; r++) { int idx = tid + r * 256; delta[idx] = acc[r]; }
    __syncthreads();
    if (tid < OO) {
        int o = tid;
        y1[o] = 0.f; y2[o] = 0.f;
        __syncwarp();
        for (int t = 0; t < TFIX; t++) {
            float a = delta[t * OO + o];
            #pragma unroll
            for (int i = 0; i < OO; i++)
                a += m_y[o * 64 + i] * y1[i] + m_y[o * 64 + 32 + i] * y2[i];
            __syncwarp();
            y2[o] = y1[o];
            __syncwarp();
            y1[o] = a;
            __syncwarp();
            out[((size_t)(b * LSEQ + t)) * OO + o] = a;
        }
    }
}

// ---------------- launch ------------------------------------------------------
extern "C" void kernel_launch(void* const* d_in, const int* in_sizes, int n_in,
                              void* d_out, int out_size) {
    const float* inputs  = (const float*)d_in[0];
    const float* eigvals = (const float*)d_in[1];
    const float* eigvecs = (const float*)d_in[2];
    const float* m_u     = (const float*)d_in[3];
    const float* m_phi   = (const float*)d_in[4];
    const float* m_y     = (const float*)d_in[5];
    float* out = (float*)d_out;

    k_pre    <<<TFIX + 5, 1024>>>(m_y, eigvals, eigvecs, m_phi);
    k_fft_fwd<<<512 + KK / 2, 1024>>>(inputs, eigvecs);
    k_W      <<<FH / 2, 1024>>>(eigvals, m_phi, m_u);
    k_mul    <<<FH / 4, 256>>>();
    k_ifft   <<<BB * OO / 2, 1024>>>(out);
    k_fix    <<<BB, 256>>>(inputs, m_u, m_y, out);
}